// round 11
// baseline (speedup 1.0000x reference)
#include <cuda_runtime.h>

#define BB   2
#define NN   512
#define DD   256
#define HH   4
#define HDD  64
#define HDH  256

typedef unsigned long long ull;
#define ABS2 0x7fffffff7fffffffULL

__device__ __align__(16) float g_hq[BB*NN*HDH];
__device__ __align__(16) float g_hk[BB*NN*HDH];
__device__ __align__(16) float g_hv[BB*NN*HDH];
__device__ __align__(16) float g_sq[BB*NN*HH];

__device__ __forceinline__ ull add2(ull a, ull b) {
    ull r; asm("add.rn.f32x2 %0, %1, %2;" : "=l"(r) : "l"(a), "l"(b)); return r;
}
__device__ __forceinline__ ull fma2(ull a, ull b, ull c) {
    ull r; asm("fma.rn.f32x2 %0, %1, %2, %3;" : "=l"(r) : "l"(a), "l"(b), "l"(c)); return r;
}
__device__ __forceinline__ ull pack2(float lo, float hi) {
    ull r; asm("mov.b64 %0, {%1, %2};" : "=l"(r) : "f"(lo), "f"(hi)); return r;
}
__device__ __forceinline__ float2 unpack2(ull v) {
    float2 f; asm("mov.b64 {%0, %1}, %2;" : "=f"(f.x), "=f"(f.y) : "l"(v)); return f;
}

// ---------------------------------------------------------------------------
// Kernel 1: projections + fused sq epilogue.
// Tile 8 rows x 128 cols, 128 threads, grid = 3*128*2 = 768 (5.2 blocks/SM).
// Thread tile 2x4 (fma/crossbar balanced), k-chunk 16, double-buffered.
// For m==0 (hq): each 128-col tile spans exactly heads {2ct, 2ct+1}, so the
// block computes sq = 0.6 * sum_f a[f]*hq[row,h,f] completely and writes it.
// ---------------------------------------------------------------------------
__global__ __launch_bounds__(128) void proj_kernel(
    const float* __restrict__ q, const float* __restrict__ k, const float* __restrict__ v,
    const float* __restrict__ wq, const float* __restrict__ bq,
    const float* __restrict__ wv, const float* __restrict__ bv,
    const float* __restrict__ a_in)
{
    __shared__ float sx[2][16][12];    // [buf][k][8 rows + pad] (48B rows)
    __shared__ float sw[2][16][128];   // [buf][k][col]

    int bid = blockIdx.x;
    int m   = bid >> 8;             // 0=q,1=k,2=v  (256 blocks per matrix)
    int rem = bid & 255;
    int rt  = rem >> 1;             // 128 row tiles of 8
    int ct  = rem & 1;              // 2 col tiles of 128
    int r0 = rt * 8, c0 = ct * 128;

    const float* src  = (m==0) ? q : (m==1) ? k : v;
    const float* W    = (m<2)  ? wq : wv;
    const float* bias = (m<2)  ? bq : bv;
    float* dst        = (m==0) ? g_hq : (m==1) ? g_hk : g_hv;

    int tid  = threadIdx.x;
    int w    = tid >> 5;   // warp 0..3 -> rows 2w, 2w+1
    int lane = tid & 31;
    int cx   = lane;       // cols cx*4 .. cx*4+3

    float4 b4 = *(const float4*)&bias[c0 + cx*4];
    float4 acc0 = b4, acc1 = b4;

    int xrow = tid >> 2, xdg = tid & 3;   // threads 0..31 load x (8 rows x 4 kgroups)

    // prefetch chunk 0
    float4 xr = make_float4(0.f,0.f,0.f,0.f);
    if (tid < 32) xr = *(const float4*)&src[(size_t)(r0 + xrow)*DD + xdg*4];
    float4 wr[4];
    #pragma unroll
    for (int j = 0; j < 4; j++) {
        int idx = tid + j*128;
        wr[j] = *(const float4*)&W[(size_t)(idx>>5)*DD + c0 + (idx&31)*4];
    }

    if (tid < 32) {
        sx[0][xdg*4+0][xrow] = xr.x;
        sx[0][xdg*4+1][xrow] = xr.y;
        sx[0][xdg*4+2][xrow] = xr.z;
        sx[0][xdg*4+3][xrow] = xr.w;
    }
    #pragma unroll
    for (int j = 0; j < 4; j++) {
        int idx = tid + j*128;
        *(float4*)&sw[0][idx>>5][(idx&31)*4] = wr[j];
    }
    __syncthreads();

    #pragma unroll 1
    for (int c = 0; c < 16; c++) {
        int buf = c & 1;
        if (c < 15) {
            int dbase = (c + 1) * 16;
            if (tid < 32) xr = *(const float4*)&src[(size_t)(r0 + xrow)*DD + dbase + xdg*4];
            #pragma unroll
            for (int j = 0; j < 4; j++) {
                int idx = tid + j*128;
                wr[j] = *(const float4*)&W[(size_t)(dbase + (idx>>5))*DD + c0 + (idx&31)*4];
            }
        }

        #pragma unroll
        for (int kk = 0; kk < 16; kk++) {
            float2 xv = *(const float2*)&sx[buf][kk][2*w];    // warp broadcast
            float4 wv = *(const float4*)&sw[buf][kk][cx*4];   // conflict-free
            acc0.x = fmaf(xv.x, wv.x, acc0.x);
            acc0.y = fmaf(xv.x, wv.y, acc0.y);
            acc0.z = fmaf(xv.x, wv.z, acc0.z);
            acc0.w = fmaf(xv.x, wv.w, acc0.w);
            acc1.x = fmaf(xv.y, wv.x, acc1.x);
            acc1.y = fmaf(xv.y, wv.y, acc1.y);
            acc1.z = fmaf(xv.y, wv.z, acc1.z);
            acc1.w = fmaf(xv.y, wv.w, acc1.w);
        }

        if (c < 15) {
            int nbuf = buf ^ 1;
            if (tid < 32) {
                sx[nbuf][xdg*4+0][xrow] = xr.x;
                sx[nbuf][xdg*4+1][xrow] = xr.y;
                sx[nbuf][xdg*4+2][xrow] = xr.z;
                sx[nbuf][xdg*4+3][xrow] = xr.w;
            }
            #pragma unroll
            for (int j = 0; j < 4; j++) {
                int idx = tid + j*128;
                *(float4*)&sw[nbuf][idx>>5][(idx&31)*4] = wr[j];
            }
        }
        __syncthreads();
    }

    float4* dst4 = (float4*)dst;
    size_t obase = (size_t)(r0 + 2*w) * 64 + (c0 >> 2) + cx;
    dst4[obase]      = acc0;
    dst4[obase + 64] = acc1;

    // ---- fused sq epilogue (hq only) ----
    if (m == 0) {
        int h = ct*2 + (lane >> 4);                 // head of this lane's columns
        float4 av = *(const float4*)&a_in[(lane*4) & 63];
        float p0 = acc0.x*av.x + acc0.y*av.y + acc0.z*av.z + acc0.w*av.w;
        float p1 = acc1.x*av.x + acc1.y*av.y + acc1.z*av.z + acc1.w*av.w;
        #pragma unroll
        for (int o = 8; o; o >>= 1) {
            p0 += __shfl_xor_sync(0xffffffffu, p0, o);
            p1 += __shfl_xor_sync(0xffffffffu, p1, o);
        }
        if ((lane & 15) == 0) {
            g_sq[(r0 + 2*w + 0)*HH + h] = 0.6f * p0;
            g_sq[(r0 + 2*w + 1)*HH + h] = 0.6f * p1;
        }
    }
}

// ---------------------------------------------------------------------------
// Kernel 2: main GAT — r9-measured structure (synchronous staging; best).
// Block per (b,h,16-row i-tile) = 256 blocks, 256 thr, 2 blocks/SM, 2-pass.
// ---------------------------------------------------------------------------
__global__ __launch_bounds__(256, 2) void gat_main(float* __restrict__ out_h,
                                                   float* __restrict__ out_e,
                                                   const float* __restrict__ a_in)
{
    extern __shared__ float sm[];
    float* sh_e  = sm;                    // 16*516
    float* sh_x  = sh_e + 16*516;         // 128*64
    float* sh_hk = sh_x + 128*64;         // 16*68
    float* sh_sq = sh_hk + 16*68;         // 512
    float* sh_p  = sh_sq + 512;           // 16*64
    float* sh_aa = sh_p + 16*64;          // 64
    // total 19136 floats = 76544 B

    int bid = blockIdx.x;
    int b   = bid >> 7;
    int h   = (bid >> 5) & 3;
    int i0  = (bid & 31) * 16;
    int tid = threadIdx.x;
    int lane = tid & 31;
    int wid  = tid >> 5;

    {
        int r = tid >> 4, fgi = tid & 15;
        float4 kv = ((const float4*)(g_hk + (size_t)(b*NN + i0 + r)*HDH + h*HDD))[fgi];
        *(float4*)&sh_hk[r*68 + fgi*4] = kv;
    }
    for (int t = tid; t < NN; t += 256)
        sh_sq[t] = g_sq[(b*NN + t)*HH + h];
    if (tid < HDD) sh_aa[tid] = 0.4f * a_in[tid];
    __syncthreads();

    int ii = lane & 15;
    int jh = lane >> 4;

    // ---- phase A: logits over 4 hq chunks of 128 rows ----
    #pragma unroll 1
    for (int cs = 0; cs < NN; cs += 128) {
        __syncthreads();
        for (int t = tid; t < 128*16; t += 256) {
            int r = t >> 4, fgi = t & 15;
            ((float4*)sh_x)[t] =
                ((const float4*)(g_hq + (size_t)(b*NN + cs + r)*HDH + h*HDD))[fgi];
        }
        __syncthreads();

        float accj[8];
        #pragma unroll 1
        for (int pass = 0; pass < 2; pass++) {
            ull kr[16], aw[16];
            {
                const ulonglong2* kp = (const ulonglong2*)(sh_hk + ii*68 + pass*32);
                const ulonglong2* ap = (const ulonglong2*)(sh_aa + pass*32);
                #pragma unroll
                for (int g = 0; g < 8; g++) {
                    ulonglong2 kk = kp[g];
                    kr[2*g] = kk.x; kr[2*g+1] = kk.y;
                    ulonglong2 av = ap[g];
                    aw[2*g] = av.x; aw[2*g+1] = av.y;
                }
            }
            #pragma unroll 2
            for (int t = 0; t < 8; t++) {
                int jj = wid*16 + t*2 + jh;
                const ulonglong2* q2 = (const ulonglong2*)(sh_x + jj*64 + pass*32);
                ull acc0 = 0ULL, acc1 = 0ULL;
                #pragma unroll
                for (int g = 0; g < 8; g++) {
                    ulonglong2 qq = q2[g];
                    ull t0 = add2(qq.x, kr[2*g]) & ABS2;
                    acc0 = fma2(aw[2*g], t0, acc0);
                    ull t1 = add2(qq.y, kr[2*g+1]) & ABS2;
                    acc1 = fma2(aw[2*g+1], t1, acc1);
                }
                float2 a0 = unpack2(acc0), a1 = unpack2(acc1);
                float s = (a0.x + a0.y) + (a1.x + a1.y);
                if (pass == 0) accj[t] = s;
                else           accj[t] += s;
            }
        }
        #pragma unroll
        for (int t = 0; t < 8; t++) {
            int j = cs + wid*16 + t*2 + jh;
            sh_e[ii*516 + j] = accj[t] + sh_sq[j];
        }
    }
    __syncthreads();

    // ---- phase B: row softmax (warp w -> rows 2w, 2w+1) ----
    #pragma unroll
    for (int rr = 0; rr < 2; rr++) {
        float* row = sh_e + (2*wid + rr)*516;
        float mx = -1e30f;
        for (int j = lane; j < NN; j += 32) mx = fmaxf(mx, row[j]);
        #pragma unroll
        for (int o = 16; o; o >>= 1) mx = fmaxf(mx, __shfl_xor_sync(0xffffffffu, mx, o));
        float s = 0.f;
        for (int j = lane; j < NN; j += 32) {
            float ex = __expf(row[j] - mx);
            row[j] = ex;
            s += ex;
        }
        #pragma unroll
        for (int o = 16; o; o >>= 1) s += __shfl_xor_sync(0xffffffffu, s, o);
        float inv = 1.f / s;
        for (int j = lane; j < NN; j += 32) row[j] *= inv;
    }
    __syncthreads();

    // ---- phase C1: write e [B,N,N,H] ----
    {
        float* ebase = out_e + ((size_t)(b*NN + i0) * NN) * HH + h;
        for (int t = tid; t < 16*512; t += 256) {
            int i = t >> 9, j = t & 511;
            ebase[(size_t)(i*NN + j) * HH] = sh_e[i*516 + j];
        }
    }

    // ---- phase C2: AV over 4 hv chunks; warps split j halves; smem reduce ----
    {
        int wq = wid & 3;
        int jhalf = wid >> 2;
        int r0 = 2*wq + (lane >> 4);
        int r1 = r0 + 8;
        int fg = lane & 15;

        ull a00 = 0ULL, a01 = 0ULL, a10 = 0ULL, a11 = 0ULL;

        #pragma unroll 1
        for (int cs = 0; cs < NN; cs += 128) {
            __syncthreads();
            for (int t = tid; t < 128*16; t += 256) {
                int r = t >> 4, fgi = t & 15;
                ((float4*)sh_x)[t] =
                    ((const float4*)(g_hv + (size_t)(b*NN + cs + r)*HDH + h*HDD))[fgi];
            }
            __syncthreads();

            int jb = jhalf * 64;
            #pragma unroll 2
            for (int qv = 0; qv < 64; qv += 4) {
                int jj = jb + qv;
                float4 e0 = *(const float4*)&sh_e[r0*516 + cs + jj];
                float4 e1 = *(const float4*)&sh_e[r1*516 + cs + jj];
                {
                    ulonglong2 vv = *(const ulonglong2*)(sh_x + (jj+0)*64 + fg*4);
                    ull ev0 = pack2(e0.x, e0.x), ev1 = pack2(e1.x, e1.x);
                    a00 = fma2(ev0, vv.x, a00); a01 = fma2(ev0, vv.y, a01);
                    a10 = fma2(ev1, vv.x, a10); a11 = fma2(ev1, vv.y, a11);
                }
                {
                    ulonglong2 vv = *(const ulonglong2*)(sh_x + (jj+1)*64 + fg*4);
                    ull ev0 = pack2(e0.y, e0.y), ev1 = pack2(e1.y, e1.y);
                    a00 = fma2(ev0, vv.x, a00); a01 = fma2(ev0, vv.y, a01);
                    a10 = fma2(ev1, vv.x, a10); a11 = fma2(ev1, vv.y, a11);
                }
                {
                    ulonglong2 vv = *(const ulonglong2*)(sh_x + (jj+2)*64 + fg*4);
                    ull ev0 = pack2(e0.z, e0.z), ev1 = pack2(e1.z, e1.z);
                    a00 = fma2(ev0, vv.x, a00); a01 = fma2(ev0, vv.y, a01);
                    a10 = fma2(ev1, vv.x, a10); a11 = fma2(ev1, vv.y, a11);
                }
                {
                    ulonglong2 vv = *(const ulonglong2*)(sh_x + (jj+3)*64 + fg*4);
                    ull ev0 = pack2(e0.w, e0.w), ev1 = pack2(e1.w, e1.w);
                    a00 = fma2(ev0, vv.x, a00); a01 = fma2(ev0, vv.y, a01);
                    a10 = fma2(ev1, vv.x, a10); a11 = fma2(ev1, vv.y, a11);
                }
            }
        }
        __syncthreads();
        if (jhalf == 1) {
            *(ulonglong2*)&sh_p[r0*64 + fg*4] = make_ulonglong2(a00, a01);
            *(ulonglong2*)&sh_p[r1*64 + fg*4] = make_ulonglong2(a10, a11);
        }
        __syncthreads();
        if (jhalf == 0) {
            ulonglong2 p0 = *(const ulonglong2*)&sh_p[r0*64 + fg*4];
            ulonglong2 p1 = *(const ulonglong2*)&sh_p[r1*64 + fg*4];
            a00 = add2(a00, p0.x); a01 = add2(a01, p0.y);
            a10 = add2(a10, p1.x); a11 = add2(a11, p1.y);
            float2 f0 = unpack2(a00), f1 = unpack2(a01);
            float2 f2 = unpack2(a10), f3 = unpack2(a11);
            float4 ra = make_float4(fmaxf(f0.x,0.f), fmaxf(f0.y,0.f),
                                    fmaxf(f1.x,0.f), fmaxf(f1.y,0.f));
            float4 rb = make_float4(fmaxf(f2.x,0.f), fmaxf(f2.y,0.f),
                                    fmaxf(f3.x,0.f), fmaxf(f3.y,0.f));
            *(float4*)&out_h[(size_t)(b*NN + i0 + r0)*HDH + h*HDD + fg*4] = ra;
            *(float4*)&out_h[(size_t)(b*NN + i0 + r1)*HDH + h*HDD + fg*4] = rb;
        }
    }
}

// ---------------------------------------------------------------------------
extern "C" void kernel_launch(void* const* d_in, const int* in_sizes, int n_in,
                              void* d_out, int out_size)
{
    const float* q  = (const float*)d_in[0];
    const float* k  = (const float*)d_in[1];
    const float* v  = (const float*)d_in[2];
    const float* wq = (const float*)d_in[3];
    const float* bq = (const float*)d_in[4];
    const float* wv = (const float*)d_in[5];
    const float* bv = (const float*)d_in[6];
    const float* a  = (const float*)d_in[7];

    float* out_h = (float*)d_out;
    float* out_e = out_h + (size_t)BB*NN*HDH;

    const int smem_main = (16*516 + 128*64 + 16*68 + 512 + 16*64 + 64) * (int)sizeof(float); // 76544
    cudaFuncSetAttribute(gat_main, cudaFuncAttributeMaxDynamicSharedMemorySize, smem_main);

    proj_kernel<<<768, 128>>>(q, k, v, wq, bq, wv, bv, a);
    gat_main<<<256, 256, smem_main>>>(out_h, out_e, a);
}

// round 12
// speedup vs baseline: 1.0267x; 1.0267x over previous
#include <cuda_runtime.h>

#define BB   2
#define NN   512
#define DD   256
#define HH   4
#define HDD  64
#define HDH  256

typedef unsigned long long ull;
#define ABS2 0x7fffffff7fffffffULL

__device__ __align__(16) float g_hq[BB*NN*HDH];
__device__ __align__(16) float g_hk[BB*NN*HDH];
__device__ __align__(16) float g_hv[BB*NN*HDH];
__device__ __align__(16) float g_sq[BB*NN*HH];

__device__ __forceinline__ ull add2(ull a, ull b) {
    ull r; asm("add.rn.f32x2 %0, %1, %2;" : "=l"(r) : "l"(a), "l"(b)); return r;
}
__device__ __forceinline__ ull fma2(ull a, ull b, ull c) {
    ull r; asm("fma.rn.f32x2 %0, %1, %2, %3;" : "=l"(r) : "l"(a), "l"(b), "l"(c)); return r;
}
__device__ __forceinline__ ull pack2(float lo, float hi) {
    ull r; asm("mov.b64 %0, {%1, %2};" : "=l"(r) : "f"(lo), "f"(hi)); return r;
}
__device__ __forceinline__ float2 unpack2(ull v) {
    float2 f; asm("mov.b64 {%0, %1}, %2;" : "=f"(f.x), "=f"(f.y) : "l"(v)); return f;
}
__device__ __forceinline__ void cp16(unsigned s, const void* g) {
    asm volatile("cp.async.ca.shared.global [%0], [%1], 16;" :: "r"(s), "l"(g));
}
#define CP_COMMIT() asm volatile("cp.async.commit_group;")
#define CP_WAIT1()  asm volatile("cp.async.wait_group 1;")
#define CP_WAIT0()  asm volatile("cp.async.wait_group 0;")

// ---------------------------------------------------------------------------
// Kernel 1: projections — r10-exact (measured 19.0us) + fused sq epilogue.
// 16x128 tiles, 128 threads, 4x4 thread tile, grid = 384 balanced blocks.
// For m==0: tile's 128 cols = exactly heads {2ct,2ct+1}; block computes
// sq = 0.6 * sum_f a[f]*hq[row,h,f] fully in-register and writes g_sq.
// ---------------------------------------------------------------------------
__global__ __launch_bounds__(128) void proj_kernel(
    const float* __restrict__ q, const float* __restrict__ k, const float* __restrict__ v,
    const float* __restrict__ wq, const float* __restrict__ bq,
    const float* __restrict__ wv, const float* __restrict__ bv,
    const float* __restrict__ a_in)
{
    __shared__ float sx[2][16][20];
    __shared__ float sw[2][16][128];

    int bid = blockIdx.x;
    int m   = bid >> 7;
    int rem = bid & 127;
    int rt  = rem >> 1;
    int ct  = rem & 1;
    int r0 = rt * 16, c0 = ct * 128;

    const float* src  = (m==0) ? q : (m==1) ? k : v;
    const float* W    = (m<2)  ? wq : wv;
    const float* bias = (m<2)  ? bq : bv;
    float* dst        = (m==0) ? g_hq : (m==1) ? g_hk : g_hv;

    int tid = threadIdx.x;
    int ry  = tid >> 5;    // 0..3 -> rows ry*4 .. ry*4+3
    int cx  = tid & 31;    // cols cx*4 .. cx*4+3

    float4 b4 = *(const float4*)&bias[c0 + cx*4];
    float4 acc0 = b4, acc1 = b4, acc2 = b4, acc3 = b4;

    int xrow = tid >> 2, xdg = tid & 3;

    float4 xr = make_float4(0.f,0.f,0.f,0.f);
    if (tid < 64) xr = *(const float4*)&src[(size_t)(r0 + xrow)*DD + xdg*4];
    float4 wr[4];
    #pragma unroll
    for (int j = 0; j < 4; j++) {
        int idx = tid + j*128;
        wr[j] = *(const float4*)&W[(size_t)(idx>>5)*DD + c0 + (idx&31)*4];
    }

    if (tid < 64) {
        sx[0][xdg*4+0][xrow] = xr.x;
        sx[0][xdg*4+1][xrow] = xr.y;
        sx[0][xdg*4+2][xrow] = xr.z;
        sx[0][xdg*4+3][xrow] = xr.w;
    }
    #pragma unroll
    for (int j = 0; j < 4; j++) {
        int idx = tid + j*128;
        *(float4*)&sw[0][idx>>5][(idx&31)*4] = wr[j];
    }
    __syncthreads();

    #pragma unroll 1
    for (int c = 0; c < 16; c++) {
        int buf = c & 1;
        if (c < 15) {
            int dbase = (c + 1) * 16;
            if (tid < 64) xr = *(const float4*)&src[(size_t)(r0 + xrow)*DD + dbase + xdg*4];
            #pragma unroll
            for (int j = 0; j < 4; j++) {
                int idx = tid + j*128;
                wr[j] = *(const float4*)&W[(size_t)(dbase + (idx>>5))*DD + c0 + (idx&31)*4];
            }
        }

        #pragma unroll
        for (int kk = 0; kk < 16; kk++) {
            float4 xv = *(const float4*)&sx[buf][kk][ry*4];
            float4 wv = *(const float4*)&sw[buf][kk][cx*4];
            acc0.x = fmaf(xv.x, wv.x, acc0.x);
            acc0.y = fmaf(xv.x, wv.y, acc0.y);
            acc0.z = fmaf(xv.x, wv.z, acc0.z);
            acc0.w = fmaf(xv.x, wv.w, acc0.w);
            acc1.x = fmaf(xv.y, wv.x, acc1.x);
            acc1.y = fmaf(xv.y, wv.y, acc1.y);
            acc1.z = fmaf(xv.y, wv.z, acc1.z);
            acc1.w = fmaf(xv.y, wv.w, acc1.w);
            acc2.x = fmaf(xv.z, wv.x, acc2.x);
            acc2.y = fmaf(xv.z, wv.y, acc2.y);
            acc2.z = fmaf(xv.z, wv.z, acc2.z);
            acc2.w = fmaf(xv.z, wv.w, acc2.w);
            acc3.x = fmaf(xv.w, wv.x, acc3.x);
            acc3.y = fmaf(xv.w, wv.y, acc3.y);
            acc3.z = fmaf(xv.w, wv.z, acc3.z);
            acc3.w = fmaf(xv.w, wv.w, acc3.w);
        }

        if (c < 15) {
            int nbuf = buf ^ 1;
            if (tid < 64) {
                sx[nbuf][xdg*4+0][xrow] = xr.x;
                sx[nbuf][xdg*4+1][xrow] = xr.y;
                sx[nbuf][xdg*4+2][xrow] = xr.z;
                sx[nbuf][xdg*4+3][xrow] = xr.w;
            }
            #pragma unroll
            for (int j = 0; j < 4; j++) {
                int idx = tid + j*128;
                *(float4*)&sw[nbuf][idx>>5][(idx&31)*4] = wr[j];
            }
        }
        __syncthreads();
    }

    float4* dst4 = (float4*)dst;
    size_t obase = (size_t)(r0 + ry*4) * 64 + (c0 >> 2) + cx;
    dst4[obase + 0*64] = acc0;
    dst4[obase + 1*64] = acc1;
    dst4[obase + 2*64] = acc2;
    dst4[obase + 3*64] = acc3;

    // ---- fused sq epilogue (q projection only) ----
    if (m == 0) {
        int lane = cx;
        int h = ct*2 + (lane >> 4);
        float4 av = *(const float4*)&a_in[(lane*4) & 63];
        float p0 = acc0.x*av.x + acc0.y*av.y + acc0.z*av.z + acc0.w*av.w;
        float p1 = acc1.x*av.x + acc1.y*av.y + acc1.z*av.z + acc1.w*av.w;
        float p2 = acc2.x*av.x + acc2.y*av.y + acc2.z*av.z + acc2.w*av.w;
        float p3 = acc3.x*av.x + acc3.y*av.y + acc3.z*av.z + acc3.w*av.w;
        #pragma unroll
        for (int o = 8; o; o >>= 1) {
            p0 += __shfl_xor_sync(0xffffffffu, p0, o);
            p1 += __shfl_xor_sync(0xffffffffu, p1, o);
            p2 += __shfl_xor_sync(0xffffffffu, p2, o);
            p3 += __shfl_xor_sync(0xffffffffu, p3, o);
        }
        if ((lane & 15) == 0) {
            int rb = r0 + ry*4;
            g_sq[(rb+0)*HH + h] = 0.6f * p0;
            g_sq[(rb+1)*HH + h] = 0.6f * p1;
            g_sq[(rb+2)*HH + h] = 0.6f * p2;
            g_sq[(rb+3)*HH + h] = 0.6f * p3;
        }
    }
}

// ---------------------------------------------------------------------------
// Kernel 2: main GAT — phase A reads hq DIRECTLY from global (each element
// used once per block; 16-lane broadcast LDG) -> barrier-free phase A.
// hv (8x reuse) staged via cp.async double-buffer, both chunks prefetched
// at kernel start. Block per (b,h,16 i-rows) = 256 blocks, 256 thr, 2/SM.
// ---------------------------------------------------------------------------
__global__ __launch_bounds__(256, 2) void gat_main(float* __restrict__ out_h,
                                                   float* __restrict__ out_e,
                                                   const float* __restrict__ a_in)
{
    extern __shared__ float sm[];
    float* sh_e  = sm;                    // 16*516
    float* sh_x  = sh_e + 16*516;         // 2*128*64 (hv double buffer)
    float* sh_hk = sh_x + 2*128*64;       // 16*68
    float* sh_sq = sh_hk + 16*68;         // 512
    float* sh_p  = sh_sq + 512;           // 16*64
    float* sh_aa = sh_p + 16*64;          // 64
    // total 27328 floats = 109312 B

    int bid = blockIdx.x;
    int b   = bid >> 7;
    int h   = (bid >> 5) & 3;
    int i0  = (bid & 31) * 16;
    int tid = threadIdx.x;
    int lane = tid & 31;
    int wid  = tid >> 5;

    unsigned xsb = (unsigned)__cvta_generic_to_shared(sh_x);
    int sr = tid >> 4, sf = tid & 15;

    // issue hv chunks 0 and 1 immediately — they fly during phase A + softmax
    {
        const float* gsrc = g_hv + (size_t)(b*NN)*HDH + h*HDD;
        #pragma unroll
        for (int rr = 0; rr < 8; rr++) {
            int r = rr*16 + sr;
            cp16(xsb + (unsigned)((r*16 + sf)*16), gsrc + (size_t)r*HDH + sf*4);
        }
        CP_COMMIT();
        gsrc += (size_t)128*HDH;
        #pragma unroll
        for (int rr = 0; rr < 8; rr++) {
            int r = rr*16 + sr;
            cp16(xsb + 32768u + (unsigned)((r*16 + sf)*16), gsrc + (size_t)r*HDH + sf*4);
        }
        CP_COMMIT();
    }

    // stage hk [16x64] (stride 68), sq[512], aa[64]
    {
        int r = tid >> 4, fgi = tid & 15;
        float4 kv = ((const float4*)(g_hk + (size_t)(b*NN + i0 + r)*HDH + h*HDD))[fgi];
        *(float4*)&sh_hk[r*68 + fgi*4] = kv;
    }
    for (int t = tid; t < NN; t += 256)
        sh_sq[t] = g_sq[(b*NN + t)*HH + h];
    if (tid < HDD) sh_aa[tid] = 0.4f * a_in[tid];
    __syncthreads();

    int ii = lane & 15;
    int jh = lane >> 4;
    const float* qbase = g_hq + (size_t)(b*NN)*HDH + h*HDD;

    // ---- phase A: logits, direct LDG from g_hq (no staging, no barriers) ----
    #pragma unroll 1
    for (int cs = 0; cs < NN; cs += 128) {
        float accj[8];
        #pragma unroll 1
        for (int pass = 0; pass < 2; pass++) {
            ull kr[16], aw[16];
            {
                const ulonglong2* kp = (const ulonglong2*)(sh_hk + ii*68 + pass*32);
                const ulonglong2* ap = (const ulonglong2*)(sh_aa + pass*32);
                #pragma unroll
                for (int g = 0; g < 8; g++) {
                    ulonglong2 kk = kp[g];
                    kr[2*g] = kk.x; kr[2*g+1] = kk.y;
                    ulonglong2 av = ap[g];
                    aw[2*g] = av.x; aw[2*g+1] = av.y;
                }
            }
            #pragma unroll 2
            for (int t = 0; t < 8; t++) {
                int j = cs + wid*16 + t*2 + jh;
                const ulonglong2* qg = (const ulonglong2*)(qbase + (size_t)j*HDH + pass*32);
                ulonglong2 qA = qg[0], qB = qg[1], qC = qg[2], qD = qg[3];
                ulonglong2 qE = qg[4], qF = qg[5], qG = qg[6], qH = qg[7];
                ull acc0 = 0ULL, acc1 = 0ULL;
                acc0 = fma2(aw[0],  add2(qA.x, kr[0])  & ABS2, acc0);
                acc1 = fma2(aw[1],  add2(qA.y, kr[1])  & ABS2, acc1);
                acc0 = fma2(aw[2],  add2(qB.x, kr[2])  & ABS2, acc0);
                acc1 = fma2(aw[3],  add2(qB.y, kr[3])  & ABS2, acc1);
                acc0 = fma2(aw[4],  add2(qC.x, kr[4])  & ABS2, acc0);
                acc1 = fma2(aw[5],  add2(qC.y, kr[5])  & ABS2, acc1);
                acc0 = fma2(aw[6],  add2(qD.x, kr[6])  & ABS2, acc0);
                acc1 = fma2(aw[7],  add2(qD.y, kr[7])  & ABS2, acc1);
                acc0 = fma2(aw[8],  add2(qE.x, kr[8])  & ABS2, acc0);
                acc1 = fma2(aw[9],  add2(qE.y, kr[9])  & ABS2, acc1);
                acc0 = fma2(aw[10], add2(qF.x, kr[10]) & ABS2, acc0);
                acc1 = fma2(aw[11], add2(qF.y, kr[11]) & ABS2, acc1);
                acc0 = fma2(aw[12], add2(qG.x, kr[12]) & ABS2, acc0);
                acc1 = fma2(aw[13], add2(qG.y, kr[13]) & ABS2, acc1);
                acc0 = fma2(aw[14], add2(qH.x, kr[14]) & ABS2, acc0);
                acc1 = fma2(aw[15], add2(qH.y, kr[15]) & ABS2, acc1);
                float2 a0 = unpack2(acc0), a1 = unpack2(acc1);
                float s = (a0.x + a0.y) + (a1.x + a1.y);
                if (pass == 0) accj[t] = s;
                else           accj[t] += s;
            }
        }
        #pragma unroll
        for (int t = 0; t < 8; t++) {
            int j = cs + wid*16 + t*2 + jh;
            sh_e[ii*516 + j] = accj[t] + sh_sq[j];
        }
    }
    __syncthreads();

    // ---- phase B: row softmax (warp w -> rows 2w, 2w+1) ----
    #pragma unroll
    for (int rr = 0; rr < 2; rr++) {
        float* row = sh_e + (2*wid + rr)*516;
        float mx = -1e30f;
        for (int j = lane; j < NN; j += 32) mx = fmaxf(mx, row[j]);
        #pragma unroll
        for (int o = 16; o; o >>= 1) mx = fmaxf(mx, __shfl_xor_sync(0xffffffffu, mx, o));
        float s = 0.f;
        for (int j = lane; j < NN; j += 32) {
            float ex = __expf(row[j] - mx);
            row[j] = ex;
            s += ex;
        }
        #pragma unroll
        for (int o = 16; o; o >>= 1) s += __shfl_xor_sync(0xffffffffu, s, o);
        float inv = 1.f / s;
        for (int j = lane; j < NN; j += 32) row[j] *= inv;
    }
    __syncthreads();

    // ---- phase C1: write e [B,N,N,H] (overlaps in-flight hv copies) ----
    {
        float* ebase = out_e + ((size_t)(b*NN + i0) * NN) * HH + h;
        for (int t = tid; t < 16*512; t += 256) {
            int i = t >> 9, j = t & 511;
            ebase[(size_t)(i*NN + j) * HH] = sh_e[i*516 + j];
        }
    }

    // ---- phase C2: AV over 4 hv chunks (double-buffered); j-half split ----
    {
        int wq = wid & 3;
        int jhalf = wid >> 2;
        int r0 = 2*wq + (lane >> 4);
        int r1 = r0 + 8;
        int fg = lane & 15;

        ull a00 = 0ULL, a01 = 0ULL, a10 = 0ULL, a11 = 0ULL;

        #pragma unroll 1
        for (int c = 0; c < 4; c++) {
            if (c < 3) { CP_WAIT1(); } else { CP_WAIT0(); }
            __syncthreads();

            const float* xb = sh_x + (c&1)*8192;
            int cs = c*128;
            int jb = jhalf * 64;

            #pragma unroll 2
            for (int qv = 0; qv < 64; qv += 4) {
                int jj = jb + qv;
                float4 e0 = *(const float4*)&sh_e[r0*516 + cs + jj];
                float4 e1 = *(const float4*)&sh_e[r1*516 + cs + jj];
                {
                    ulonglong2 vv = *(const ulonglong2*)(xb + (jj+0)*64 + fg*4);
                    ull ev0 = pack2(e0.x, e0.x), ev1 = pack2(e1.x, e1.x);
                    a00 = fma2(ev0, vv.x, a00); a01 = fma2(ev0, vv.y, a01);
                    a10 = fma2(ev1, vv.x, a10); a11 = fma2(ev1, vv.y, a11);
                }
                {
                    ulonglong2 vv = *(const ulonglong2*)(xb + (jj+1)*64 + fg*4);
                    ull ev0 = pack2(e0.y, e0.y), ev1 = pack2(e1.y, e1.y);
                    a00 = fma2(ev0, vv.x, a00); a01 = fma2(ev0, vv.y, a01);
                    a10 = fma2(ev1, vv.x, a10); a11 = fma2(ev1, vv.y, a11);
                }
                {
                    ulonglong2 vv = *(const ulonglong2*)(xb + (jj+2)*64 + fg*4);
                    ull ev0 = pack2(e0.z, e0.z), ev1 = pack2(e1.z, e1.z);
                    a00 = fma2(ev0, vv.x, a00); a01 = fma2(ev0, vv.y, a01);
                    a10 = fma2(ev1, vv.x, a10); a11 = fma2(ev1, vv.y, a11);
                }
                {
                    ulonglong2 vv = *(const ulonglong2*)(xb + (jj+3)*64 + fg*4);
                    ull ev0 = pack2(e0.w, e0.w), ev1 = pack2(e1.w, e1.w);
                    a00 = fma2(ev0, vv.x, a00); a01 = fma2(ev0, vv.y, a01);
                    a10 = fma2(ev1, vv.x, a10); a11 = fma2(ev1, vv.y, a11);
                }
            }
            __syncthreads();

            if (c < 2) {
                const float* gsrc = g_hv + (size_t)(b*NN + (c+2)*128)*HDH + h*HDD;
                unsigned boff = (unsigned)((c&1) * 32768);
                #pragma unroll
                for (int rr = 0; rr < 8; rr++) {
                    int r = rr*16 + sr;
                    cp16(xsb + boff + (unsigned)((r*16 + sf)*16), gsrc + (size_t)r*HDH + sf*4);
                }
                CP_COMMIT();
            }
        }

        if (jhalf == 1) {
            *(ulonglong2*)&sh_p[r0*64 + fg*4] = make_ulonglong2(a00, a01);
            *(ulonglong2*)&sh_p[r1*64 + fg*4] = make_ulonglong2(a10, a11);
        }
        __syncthreads();
        if (jhalf == 0) {
            ulonglong2 p0 = *(const ulonglong2*)&sh_p[r0*64 + fg*4];
            ulonglong2 p1 = *(const ulonglong2*)&sh_p[r1*64 + fg*4];
            a00 = add2(a00, p0.x); a01 = add2(a01, p0.y);
            a10 = add2(a10, p1.x); a11 = add2(a11, p1.y);
            float2 f0 = unpack2(a00), f1 = unpack2(a01);
            float2 f2 = unpack2(a10), f3 = unpack2(a11);
            float4 ra = make_float4(fmaxf(f0.x,0.f), fmaxf(f0.y,0.f),
                                    fmaxf(f1.x,0.f), fmaxf(f1.y,0.f));
            float4 rb = make_float4(fmaxf(f2.x,0.f), fmaxf(f2.y,0.f),
                                    fmaxf(f3.x,0.f), fmaxf(f3.y,0.f));
            *(float4*)&out_h[(size_t)(b*NN + i0 + r0)*HDH + h*HDD + fg*4] = ra;
            *(float4*)&out_h[(size_t)(b*NN + i0 + r1)*HDH + h*HDD + fg*4] = rb;
        }
    }
}

// ---------------------------------------------------------------------------
extern "C" void kernel_launch(void* const* d_in, const int* in_sizes, int n_in,
                              void* d_out, int out_size)
{
    const float* q  = (const float*)d_in[0];
    const float* k  = (const float*)d_in[1];
    const float* v  = (const float*)d_in[2];
    const float* wq = (const float*)d_in[3];
    const float* bq = (const float*)d_in[4];
    const float* wv = (const float*)d_in[5];
    const float* bv = (const float*)d_in[6];
    const float* a  = (const float*)d_in[7];

    float* out_h = (float*)d_out;
    float* out_e = out_h + (size_t)BB*NN*HDH;

    const int smem_main = (16*516 + 2*128*64 + 16*68 + 512 + 16*64 + 64) * (int)sizeof(float); // 109312
    cudaFuncSetAttribute(gat_main, cudaFuncAttributeMaxDynamicSharedMemorySize, smem_main);

    proj_kernel<<<384, 128>>>(q, k, v, wq, bq, wv, bv, a);
    gat_main<<<256, 256, smem_main>>>(out_h, out_e, a);
}

// round 14
// speedup vs baseline: 1.0698x; 1.0420x over previous
#include <cuda_runtime.h>

#define BB   2
#define NN   512
#define DD   256
#define HH   4
#define HDD  64
#define HDH  256

typedef unsigned long long ull;
#define ABS2 0x7fffffff7fffffffULL

__device__ __align__(16) float g_hq[BB*NN*HDH];
__device__ __align__(16) float g_hk[BB*NN*HDH];
__device__ __align__(16) float g_hv[BB*NN*HDH];
__device__ __align__(16) float g_sq[BB*NN*HH];

__device__ __forceinline__ ull add2(ull a, ull b) {
    ull r; asm("add.rn.f32x2 %0, %1, %2;" : "=l"(r) : "l"(a), "l"(b)); return r;
}
__device__ __forceinline__ ull fma2(ull a, ull b, ull c) {
    ull r; asm("fma.rn.f32x2 %0, %1, %2, %3;" : "=l"(r) : "l"(a), "l"(b), "l"(c)); return r;
}
__device__ __forceinline__ ull pack2(float lo, float hi) {
    ull r; asm("mov.b64 %0, {%1, %2};" : "=l"(r) : "f"(lo), "f"(hi)); return r;
}
__device__ __forceinline__ float2 unpack2(ull v) {
    float2 f; asm("mov.b64 {%0, %1}, %2;" : "=f"(f.x), "=f"(f.y) : "l"(v)); return f;
}
__device__ __forceinline__ void cp16(unsigned s, const void* g) {
    asm volatile("cp.async.ca.shared.global [%0], [%1], 16;" :: "r"(s), "l"(g));
}
#define CP_COMMIT() asm volatile("cp.async.commit_group;")
#define CP_WAIT1()  asm volatile("cp.async.wait_group 1;")
#define CP_WAIT0()  asm volatile("cp.async.wait_group 0;")

// ---------------------------------------------------------------------------
// Kernel 1: projections — r10-exact GEMM (measured 19.0us) + validated
// fused-sq epilogue (base kernel deleted). 16x128 tiles, 128 thr, 4x4
// thread tile, 384 balanced blocks.
// ---------------------------------------------------------------------------
__global__ __launch_bounds__(128) void proj_kernel(
    const float* __restrict__ q, const float* __restrict__ k, const float* __restrict__ v,
    const float* __restrict__ wq, const float* __restrict__ bq,
    const float* __restrict__ wv, const float* __restrict__ bv,
    const float* __restrict__ a_in)
{
    __shared__ float sx[2][16][20];
    __shared__ float sw[2][16][128];

    int bid = blockIdx.x;
    int m   = bid >> 7;
    int rem = bid & 127;
    int rt  = rem >> 1;
    int ct  = rem & 1;
    int r0 = rt * 16, c0 = ct * 128;

    const float* src  = (m==0) ? q : (m==1) ? k : v;
    const float* W    = (m<2)  ? wq : wv;
    const float* bias = (m<2)  ? bq : bv;
    float* dst        = (m==0) ? g_hq : (m==1) ? g_hk : g_hv;

    int tid = threadIdx.x;
    int ry  = tid >> 5;
    int cx  = tid & 31;

    float4 b4 = *(const float4*)&bias[c0 + cx*4];
    float4 acc0 = b4, acc1 = b4, acc2 = b4, acc3 = b4;

    int xrow = tid >> 2, xdg = tid & 3;

    float4 xr = make_float4(0.f,0.f,0.f,0.f);
    if (tid < 64) xr = *(const float4*)&src[(size_t)(r0 + xrow)*DD + xdg*4];
    float4 wr[4];
    #pragma unroll
    for (int j = 0; j < 4; j++) {
        int idx = tid + j*128;
        wr[j] = *(const float4*)&W[(size_t)(idx>>5)*DD + c0 + (idx&31)*4];
    }

    if (tid < 64) {
        sx[0][xdg*4+0][xrow] = xr.x;
        sx[0][xdg*4+1][xrow] = xr.y;
        sx[0][xdg*4+2][xrow] = xr.z;
        sx[0][xdg*4+3][xrow] = xr.w;
    }
    #pragma unroll
    for (int j = 0; j < 4; j++) {
        int idx = tid + j*128;
        *(float4*)&sw[0][idx>>5][(idx&31)*4] = wr[j];
    }
    __syncthreads();

    #pragma unroll 1
    for (int c = 0; c < 16; c++) {
        int buf = c & 1;
        if (c < 15) {
            int dbase = (c + 1) * 16;
            if (tid < 64) xr = *(const float4*)&src[(size_t)(r0 + xrow)*DD + dbase + xdg*4];
            #pragma unroll
            for (int j = 0; j < 4; j++) {
                int idx = tid + j*128;
                wr[j] = *(const float4*)&W[(size_t)(dbase + (idx>>5))*DD + c0 + (idx&31)*4];
            }
        }

        #pragma unroll
        for (int kk = 0; kk < 16; kk++) {
            float4 xv = *(const float4*)&sx[buf][kk][ry*4];
            float4 wv = *(const float4*)&sw[buf][kk][cx*4];
            acc0.x = fmaf(xv.x, wv.x, acc0.x);
            acc0.y = fmaf(xv.x, wv.y, acc0.y);
            acc0.z = fmaf(xv.x, wv.z, acc0.z);
            acc0.w = fmaf(xv.x, wv.w, acc0.w);
            acc1.x = fmaf(xv.y, wv.x, acc1.x);
            acc1.y = fmaf(xv.y, wv.y, acc1.y);
            acc1.z = fmaf(xv.y, wv.z, acc1.z);
            acc1.w = fmaf(xv.y, wv.w, acc1.w);
            acc2.x = fmaf(xv.z, wv.x, acc2.x);
            acc2.y = fmaf(xv.z, wv.y, acc2.y);
            acc2.z = fmaf(xv.z, wv.z, acc2.z);
            acc2.w = fmaf(xv.z, wv.w, acc2.w);
            acc3.x = fmaf(xv.w, wv.x, acc3.x);
            acc3.y = fmaf(xv.w, wv.y, acc3.y);
            acc3.z = fmaf(xv.w, wv.z, acc3.z);
            acc3.w = fmaf(xv.w, wv.w, acc3.w);
        }

        if (c < 15) {
            int nbuf = buf ^ 1;
            if (tid < 64) {
                sx[nbuf][xdg*4+0][xrow] = xr.x;
                sx[nbuf][xdg*4+1][xrow] = xr.y;
                sx[nbuf][xdg*4+2][xrow] = xr.z;
                sx[nbuf][xdg*4+3][xrow] = xr.w;
            }
            #pragma unroll
            for (int j = 0; j < 4; j++) {
                int idx = tid + j*128;
                *(float4*)&sw[nbuf][idx>>5][(idx&31)*4] = wr[j];
            }
        }
        __syncthreads();
    }

    float4* dst4 = (float4*)dst;
    size_t obase = (size_t)(r0 + ry*4) * 64 + (c0 >> 2) + cx;
    dst4[obase + 0*64] = acc0;
    dst4[obase + 1*64] = acc1;
    dst4[obase + 2*64] = acc2;
    dst4[obase + 3*64] = acc3;

    // ---- fused sq epilogue (q projection only; validated r11/r12) ----
    if (m == 0) {
        int lane = cx;
        int h = ct*2 + (lane >> 4);
        float4 av = *(const float4*)&a_in[(lane*4) & 63];
        float p0 = acc0.x*av.x + acc0.y*av.y + acc0.z*av.z + acc0.w*av.w;
        float p1 = acc1.x*av.x + acc1.y*av.y + acc1.z*av.z + acc1.w*av.w;
        float p2 = acc2.x*av.x + acc2.y*av.y + acc2.z*av.z + acc2.w*av.w;
        float p3 = acc3.x*av.x + acc3.y*av.y + acc3.z*av.z + acc3.w*av.w;
        #pragma unroll
        for (int o = 8; o; o >>= 1) {
            p0 += __shfl_xor_sync(0xffffffffu, p0, o);
            p1 += __shfl_xor_sync(0xffffffffu, p1, o);
            p2 += __shfl_xor_sync(0xffffffffu, p2, o);
            p3 += __shfl_xor_sync(0xffffffffu, p3, o);
        }
        if ((lane & 15) == 0) {
            int rb = r0 + ry*4;
            g_sq[(rb+0)*HH + h] = 0.6f * p0;
            g_sq[(rb+1)*HH + h] = 0.6f * p1;
            g_sq[(rb+2)*HH + h] = 0.6f * p2;
            g_sq[(rb+3)*HH + h] = 0.6f * p3;
        }
    }
}

// ---------------------------------------------------------------------------
// Kernel 2: main GAT — r10-exact structure (best measured as part of 64.0us):
// cp.async double-buffered staging for BOTH hq (phase A) and hv (phase C2).
// Block per (b,h,16-row i-tile) = 256 blocks, 256 thr, 2 blocks/SM, 2-pass.
// ---------------------------------------------------------------------------
__global__ __launch_bounds__(256, 2) void gat_main(float* __restrict__ out_h,
                                                   float* __restrict__ out_e,
                                                   const float* __restrict__ a_in)
{
    extern __shared__ float sm[];
    float* sh_e  = sm;                    // 16*516  = 8256
    float* sh_x  = sh_e + 16*516;         // 2*128*64 = 16384 (double buffer)
    float* sh_hk = sh_x + 2*128*64;       // 16*68   = 1088
    float* sh_sq = sh_hk + 16*68;         // 512
    float* sh_p  = sh_sq + 512;           // 16*64   = 1024
    float* sh_aa = sh_p + 16*64;          // 64
    // total 27328 floats = 109312 B

    int bid = blockIdx.x;
    int b   = bid >> 7;
    int h   = (bid >> 5) & 3;
    int i0  = (bid & 31) * 16;
    int tid = threadIdx.x;
    int lane = tid & 31;
    int wid  = tid >> 5;

    unsigned xsb = (unsigned)__cvta_generic_to_shared(sh_x);
    int sr = tid >> 4, sf = tid & 15;     // staging: 16 rows x 16 fgroups

    // prologue: async-fetch hq chunk 0 into buffer 0
    {
        const float* gsrc = g_hq + (size_t)(b*NN)*HDH + h*HDD;
        #pragma unroll
        for (int rr = 0; rr < 8; rr++) {
            int r = rr*16 + sr;
            cp16(xsb + (unsigned)((r*16 + sf)*16), gsrc + (size_t)r*HDH + sf*4);
        }
        CP_COMMIT();
    }

    // stage hk [16 x 64] (stride 68), sq[512], aa[64]
    {
        int r = tid >> 4, fgi = tid & 15;
        float4 kv = ((const float4*)(g_hk + (size_t)(b*NN + i0 + r)*HDH + h*HDD))[fgi];
        *(float4*)&sh_hk[r*68 + fgi*4] = kv;
    }
    for (int t = tid; t < NN; t += 256)
        sh_sq[t] = g_sq[(b*NN + t)*HH + h];
    if (tid < HDD) sh_aa[tid] = 0.4f * a_in[tid];

    int ii = lane & 15;
    int jh = lane >> 4;

    // ---- phase A: logits over 4 hq chunks of 128 rows, pipelined ----
    #pragma unroll 1
    for (int c = 0; c < 4; c++) {
        if (c < 3) {
            const float* gsrc = g_hq + (size_t)(b*NN + (c+1)*128)*HDH + h*HDD;
            unsigned boff = (unsigned)(((c+1)&1) * 32768);
            #pragma unroll
            for (int rr = 0; rr < 8; rr++) {
                int r = rr*16 + sr;
                cp16(xsb + boff + (unsigned)((r*16 + sf)*16), gsrc + (size_t)r*HDH + sf*4);
            }
            CP_COMMIT();
            CP_WAIT1();
        } else {
            CP_WAIT0();
        }
        __syncthreads();

        const float* xb = sh_x + (c&1)*8192;
        int cs = c*128;

        float accj[8];
        #pragma unroll 1
        for (int pass = 0; pass < 2; pass++) {
            ull kr[16], aw[16];
            {
                const ulonglong2* kp = (const ulonglong2*)(sh_hk + ii*68 + pass*32);
                const ulonglong2* ap = (const ulonglong2*)(sh_aa + pass*32);
                #pragma unroll
                for (int g = 0; g < 8; g++) {
                    ulonglong2 kk = kp[g];
                    kr[2*g] = kk.x; kr[2*g+1] = kk.y;
                    ulonglong2 av = ap[g];
                    aw[2*g] = av.x; aw[2*g+1] = av.y;
                }
            }
            #pragma unroll 2
            for (int t = 0; t < 8; t++) {
                int jj = wid*16 + t*2 + jh;
                const ulonglong2* q2 = (const ulonglong2*)(xb + jj*64 + pass*32);
                ull acc0 = 0ULL, acc1 = 0ULL;
                #pragma unroll
                for (int g = 0; g < 8; g++) {
                    ulonglong2 qq = q2[g];
                    ull t0 = add2(qq.x, kr[2*g]) & ABS2;
                    acc0 = fma2(aw[2*g], t0, acc0);
                    ull t1 = add2(qq.y, kr[2*g+1]) & ABS2;
                    acc1 = fma2(aw[2*g+1], t1, acc1);
                }
                float2 a0 = unpack2(acc0), a1 = unpack2(acc1);
                float s = (a0.x + a0.y) + (a1.x + a1.y);
                if (pass == 0) accj[t] = s;
                else           accj[t] += s;
            }
        }
        #pragma unroll
        for (int t = 0; t < 8; t++) {
            int j = cs + wid*16 + t*2 + jh;
            sh_e[ii*516 + j] = accj[t] + sh_sq[j];
        }
        __syncthreads();
    }

    // ---- phase B: row softmax (warp w -> rows 2w, 2w+1) ----
    #pragma unroll
    for (int rr = 0; rr < 2; rr++) {
        float* row = sh_e + (2*wid + rr)*516;
        float mx = -1e30f;
        for (int j = lane; j < NN; j += 32) mx = fmaxf(mx, row[j]);
        #pragma unroll
        for (int o = 16; o; o >>= 1) mx = fmaxf(mx, __shfl_xor_sync(0xffffffffu, mx, o));
        float s = 0.f;
        for (int j = lane; j < NN; j += 32) {
            float ex = __expf(row[j] - mx);
            row[j] = ex;
            s += ex;
        }
        #pragma unroll
        for (int o = 16; o; o >>= 1) s += __shfl_xor_sync(0xffffffffu, s, o);
        float inv = 1.f / s;
        for (int j = lane; j < NN; j += 32) row[j] *= inv;
    }
    __syncthreads();

    // ---- C: issue first hv fetch, then e-writes overlap it ----
    {
        const float* gsrc = g_hv + (size_t)(b*NN)*HDH + h*HDD;
        #pragma unroll
        for (int rr = 0; rr < 8; rr++) {
            int r = rr*16 + sr;
            cp16(xsb + (unsigned)((r*16 + sf)*16), gsrc + (size_t)r*HDH + sf*4);
        }
        CP_COMMIT();
    }

    // phase C1: write e [B,N,N,H]
    {
        float* ebase = out_e + ((size_t)(b*NN + i0) * NN) * HH + h;
        for (int t = tid; t < 16*512; t += 256) {
            int i = t >> 9, j = t & 511;
            ebase[(size_t)(i*NN + j) * HH] = sh_e[i*516 + j];
        }
    }

    // phase C2: AV over 4 hv chunks (pipelined); warps split j halves
    {
        int wq = wid & 3;
        int jhalf = wid >> 2;
        int r0 = 2*wq + (lane >> 4);
        int r1 = r0 + 8;
        int fg = lane & 15;

        ull a00 = 0ULL, a01 = 0ULL, a10 = 0ULL, a11 = 0ULL;

        #pragma unroll 1
        for (int c = 0; c < 4; c++) {
            if (c < 3) {
                const float* gsrc = g_hv + (size_t)(b*NN + (c+1)*128)*HDH + h*HDD;
                unsigned boff = (unsigned)(((c+1)&1) * 32768);
                #pragma unroll
                for (int rr = 0; rr < 8; rr++) {
                    int r = rr*16 + sr;
                    cp16(xsb + boff + (unsigned)((r*16 + sf)*16), gsrc + (size_t)r*HDH + sf*4);
                }
                CP_COMMIT();
                CP_WAIT1();
            } else {
                CP_WAIT0();
            }
            __syncthreads();

            const float* xb = sh_x + (c&1)*8192;
            int cs = c*128;

            int jb = jhalf * 64;
            #pragma unroll 2
            for (int qv = 0; qv < 64; qv += 4) {
                int jj = jb + qv;
                float4 e0 = *(const float4*)&sh_e[r0*516 + cs + jj];
                float4 e1 = *(const float4*)&sh_e[r1*516 + cs + jj];
                {
                    ulonglong2 vv = *(const ulonglong2*)(xb + (jj+0)*64 + fg*4);
                    ull ev0 = pack2(e0.x, e0.x), ev1 = pack2(e1.x, e1.x);
                    a00 = fma2(ev0, vv.x, a00); a01 = fma2(ev0, vv.y, a01);
                    a10 = fma2(ev1, vv.x, a10); a11 = fma2(ev1, vv.y, a11);
                }
                {
                    ulonglong2 vv = *(const ulonglong2*)(xb + (jj+1)*64 + fg*4);
                    ull ev0 = pack2(e0.y, e0.y), ev1 = pack2(e1.y, e1.y);
                    a00 = fma2(ev0, vv.x, a00); a01 = fma2(ev0, vv.y, a01);
                    a10 = fma2(ev1, vv.x, a10); a11 = fma2(ev1, vv.y, a11);
                }
                {
                    ulonglong2 vv = *(const ulonglong2*)(xb + (jj+2)*64 + fg*4);
                    ull ev0 = pack2(e0.z, e0.z), ev1 = pack2(e1.z, e1.z);
                    a00 = fma2(ev0, vv.x, a00); a01 = fma2(ev0, vv.y, a01);
                    a10 = fma2(ev1, vv.x, a10); a11 = fma2(ev1, vv.y, a11);
                }
                {
                    ulonglong2 vv = *(const ulonglong2*)(xb + (jj+3)*64 + fg*4);
                    ull ev0 = pack2(e0.w, e0.w), ev1 = pack2(e1.w, e1.w);
                    a00 = fma2(ev0, vv.x, a00); a01 = fma2(ev0, vv.y, a01);
                    a10 = fma2(ev1, vv.x, a10); a11 = fma2(ev1, vv.y, a11);
                }
            }
            __syncthreads();
        }

        if (jhalf == 1) {
            *(ulonglong2*)&sh_p[r0*64 + fg*4] = make_ulonglong2(a00, a01);
            *(ulonglong2*)&sh_p[r1*64 + fg*4] = make_ulonglong2(a10, a11);
        }
        __syncthreads();
        if (jhalf == 0) {
            ulonglong2 p0 = *(const ulonglong2*)&sh_p[r0*64 + fg*4];
            ulonglong2 p1 = *(const ulonglong2*)&sh_p[r1*64 + fg*4];
            a00 = add2(a00, p0.x); a01 = add2(a01, p0.y);
            a10 = add2(a10, p1.x); a11 = add2(a11, p1.y);
            float2 f0 = unpack2(a00), f1 = unpack2(a01);
            float2 f2 = unpack2(a10), f3 = unpack2(a11);
            float4 ra = make_float4(fmaxf(f0.x,0.f), fmaxf(f0.y,0.f),
                                    fmaxf(f1.x,0.f), fmaxf(f1.y,0.f));
            float4 rb = make_float4(fmaxf(f2.x,0.f), fmaxf(f2.y,0.f),
                                    fmaxf(f3.x,0.f), fmaxf(f3.y,0.f));
            *(float4*)&out_h[(size_t)(b*NN + i0 + r0)*HDH + h*HDD + fg*4] = ra;
            *(float4*)&out_h[(size_t)(b*NN + i0 + r1)*HDH + h*HDD + fg*4] = rb;
        }
    }
}

// ---------------------------------------------------------------------------
extern "C" void kernel_launch(void* const* d_in, const int* in_sizes, int n_in,
                              void* d_out, int out_size)
{
    const float* q  = (const float*)d_in[0];
    const float* k  = (const float*)d_in[1];
    const float* v  = (const float*)d_in[2];
    const float* wq = (const float*)d_in[3];
    const float* bq = (const float*)d_in[4];
    const float* wv = (const float*)d_in[5];
    const float* bv = (const float*)d_in[6];
    const float* a  = (const float*)d_in[7];

    float* out_h = (float*)d_out;
    float* out_e = out_h + (size_t)BB*NN*HDH;

    const int smem_main = (16*516 + 2*128*64 + 16*68 + 512 + 16*64 + 64) * (int)sizeof(float); // 109312
    cudaFuncSetAttribute(gat_main, cudaFuncAttributeMaxDynamicSharedMemorySize, smem_main);

    proj_kernel<<<384, 128>>>(q, k, v, wq, bq, wv, bv, a);
    gat_main<<<256, 256, smem_main>>>(out_h, out_e, a);
}